// round 12
// baseline (speedup 1.0000x reference)
#include <cuda_runtime.h>

// CustomMetaPath2Vec: loss = mean(-log(sigmoid(pos_dots)+eps)) + mean(-log(1-sigmoid(neg_dots)+eps))
// 1.2M rows x 7 random gathers of 512B embedding rows = 4.3 GB gather-bound.
//
// R9 change vs 571.6us version (profile: DRAM 79.2%, occ 51.9% @ 48 regs = 5 CTAs/SM):
//  - __launch_bounds__(256, 6): cap regs at 42 -> 6 CTAs/SM (48 warps, 75% occ).
//    This workload hides DRAM latency purely with warp parallelism; the 6th CTA
//    buys ~20% more outstanding gathers. Grid sized to exactly one wave (148*6).
//  - everything else unchanged: 4-row groups, one coalesced 28-lane index load,
//    double-buffered index prefetch, 6-way parallel transcendentals, fused
//    last-block finalize (single launch, self-resetting counter).
//
// NUMERICS (do not touch -> rel_err 0.0): s = 1.0f/(1.0f+expf(-x)) with accurate expf
// and true division; pos: -logf(s+1e-15f); neg: -logf(1.0f-s+1e-15f) (fp32
// cancellation + saturation exactly like the reference).

#define DIM      128
#define CTX      7
#define NCTX     6
#define EPSF     1e-15f
#define NTHREADS 256
#define NCTA_SM  6
#define NBLOCKS  (148 * NCTA_SM)
#define GROUP    4          // rows per warp iteration (GROUP*CTX = 28 <= 32 lanes)

__device__ double       g_part_pos[NBLOCKS];
__device__ double       g_part_neg[NBLOCKS];
__device__ unsigned int g_done = 0;   // self-resetting completion counter

// Coalesced 28-lane index load for one group (assumes group does not straddle
// the pos/neg boundary; caller guarantees or uses the generic path).
__device__ __forceinline__ int load_group_idx(
    const int* __restrict__ pos_rw, const int* __restrict__ neg_rw,
    long long r0, int pos_rows, int lane, int nlanes)
{
    const int* base = (r0 < (long long)pos_rows)
                        ? pos_rw + r0 * CTX
                        : neg_rw + (r0 - pos_rows) * CTX;
    return (lane < nlanes) ? __ldcg(base + lane) : 0;
}

__global__ __launch_bounds__(NTHREADS, NCTA_SM) void mp2v_kernel(
    const float* __restrict__ emb,
    const int*   __restrict__ pos_rw,
    const int*   __restrict__ neg_rw,
    int pos_rows, int neg_rows,
    float* __restrict__ out)
{
    const int lane = threadIdx.x & 31;
    const int wib  = threadIdx.x >> 5;
    const int wpb  = NTHREADS >> 5;

    const long long total   = (long long)pos_rows + neg_rows;
    const long long ngroups = (total + GROUP - 1) / GROUP;
    const long long gstride = (long long)gridDim.x * wpb;
    long long gidx          = (long long)blockIdx.x * wpb + wib;

    // Hot path requires: no group straddles the pos/neg boundary and no partial
    // tail group. True for the dataset (200000 % 4 == 0, 1200000 % 4 == 0).
    const bool uniform = ((pos_rows % GROUP) == 0) && ((total % GROUP) == 0);

    float accp = 0.0f, accn = 0.0f;

    if (uniform) {
        // Prime the index pipeline.
        int idx_cur = (gidx < ngroups)
            ? load_group_idx(pos_rw, neg_rw, gidx * GROUP, pos_rows, lane, GROUP * CTX)
            : 0;

        for (long long g = gidx; g < ngroups; g += gstride) {
            // Prefetch next group's indices NOW; consumed next iteration.
            const long long gn = g + gstride;
            int idx_nxt = (gn < ngroups)
                ? load_group_idx(pos_rw, neg_rw, gn * GROUP, pos_rows, lane, GROUP * CTX)
                : 0;

            const long long r0  = g * GROUP;
            const bool is_pos   = (r0 < (long long)pos_rows);  // uniform over group

            #pragma unroll
            for (int r = 0; r < GROUP; r++) {
                const int i0 = __shfl_sync(0xffffffffu, idx_cur, r * CTX);
                float4 h = __ldcg((const float4*)(emb + (long long)i0 * DIM) + lane);

                float4 cv[NCTX];
                #pragma unroll
                for (int j = 0; j < NCTX; j++) {
                    const int ij = __shfl_sync(0xffffffffu, idx_cur, r * CTX + j + 1);
                    cv[j] = __ldcg((const float4*)(emb + (long long)ij * DIM) + lane);
                }

                float p[NCTX];
                #pragma unroll
                for (int j = 0; j < NCTX; j++) {
                    float d = h.x * cv[j].x;
                    d = fmaf(h.y, cv[j].y, d);
                    d = fmaf(h.z, cv[j].z, d);
                    d = fmaf(h.w, cv[j].w, d);
                    p[j] = d;
                }

                // Butterfly reduce, 6 independent chains (ILP over SHFL latency).
                #pragma unroll
                for (int off = 16; off > 0; off >>= 1) {
                    #pragma unroll
                    for (int j = 0; j < NCTX; j++)
                        p[j] += __shfl_xor_sync(0xffffffffu, p[j], off);
                }

                // Lane j takes dot j; 6-way parallel exp/div/log.
                float x = p[0];
                #pragma unroll
                for (int j = 1; j < NCTX; j++)
                    if (lane == j) x = p[j];

                if (lane < NCTX) {
                    const float s = 1.0f / (1.0f + expf(-x));
                    if (is_pos) accp += -logf(s + EPSF);
                    else        accn += -logf(1.0f - s + EPSF);
                }
            }
            idx_cur = idx_nxt;
        }
    } else {
        // Cold generic path: per-row indexing, handles straddle + tail.
        for (long long g = gidx; g < ngroups; g += gstride) {
            const long long r0 = g * GROUP;
            const int nrows = (int)((total - r0 < GROUP) ? (total - r0) : GROUP);
            int myidx = 0;
            if (lane < nrows * CTX) {
                const int rr = lane / CTX, cc = lane % CTX;
                const long long row = r0 + rr;
                myidx = (row < (long long)pos_rows)
                          ? pos_rw[row * CTX + cc]
                          : neg_rw[(row - pos_rows) * CTX + cc];
            }
            for (int r = 0; r < nrows; r++) {
                const bool is_pos = (r0 + r) < (long long)pos_rows;
                const int i0 = __shfl_sync(0xffffffffu, myidx, r * CTX);
                float4 h = __ldcg((const float4*)(emb + (long long)i0 * DIM) + lane);
                float4 cv[NCTX];
                #pragma unroll
                for (int j = 0; j < NCTX; j++) {
                    const int ij = __shfl_sync(0xffffffffu, myidx, r * CTX + j + 1);
                    cv[j] = __ldcg((const float4*)(emb + (long long)ij * DIM) + lane);
                }
                float p[NCTX];
                #pragma unroll
                for (int j = 0; j < NCTX; j++) {
                    float d = h.x * cv[j].x;
                    d = fmaf(h.y, cv[j].y, d);
                    d = fmaf(h.z, cv[j].z, d);
                    d = fmaf(h.w, cv[j].w, d);
                    p[j] = d;
                }
                #pragma unroll
                for (int off = 16; off > 0; off >>= 1) {
                    #pragma unroll
                    for (int j = 0; j < NCTX; j++)
                        p[j] += __shfl_xor_sync(0xffffffffu, p[j], off);
                }
                float x = p[0];
                #pragma unroll
                for (int j = 1; j < NCTX; j++)
                    if (lane == j) x = p[j];
                if (lane < NCTX) {
                    const float s = 1.0f / (1.0f + expf(-x));
                    if (is_pos) accp += -logf(s + EPSF);
                    else        accn += -logf(1.0f - s + EPSF);
                }
            }
        }
    }

    // ---- Block reduction -> per-CTA partial slot ----
    double dp = (double)accp, dn = (double)accn;
    #pragma unroll
    for (int off = 16; off > 0; off >>= 1) {
        dp += __shfl_xor_sync(0xffffffffu, dp, off);
        dn += __shfl_xor_sync(0xffffffffu, dn, off);
    }

    __shared__ double s_pos[NTHREADS >> 5], s_neg[NTHREADS >> 5];
    __shared__ bool   am_last;
    if (lane == 0) { s_pos[wib] = dp; s_neg[wib] = dn; }
    __syncthreads();
    if (threadIdx.x == 0) {
        double sp = 0.0, sn = 0.0;
        #pragma unroll
        for (int w = 0; w < (NTHREADS >> 5); w++) { sp += s_pos[w]; sn += s_neg[w]; }
        g_part_pos[blockIdx.x] = sp;
        g_part_neg[blockIdx.x] = sn;
        __threadfence();
        const unsigned t = atomicAdd(&g_done, 1u);
        am_last = (t == (unsigned)(gridDim.x - 1));
    }
    __syncthreads();

    // ---- Last CTA: final reduction + output + counter reset ----
    if (am_last) {
        __threadfence();  // acquire partials from all CTAs
        double a = 0.0, b = 0.0;
        for (int i = threadIdx.x; i < (int)gridDim.x; i += NTHREADS) {
            a += g_part_pos[i];
            b += g_part_neg[i];
        }
        #pragma unroll
        for (int off = 16; off > 0; off >>= 1) {
            a += __shfl_xor_sync(0xffffffffu, a, off);
            b += __shfl_xor_sync(0xffffffffu, b, off);
        }
        if (lane == 0) { s_pos[wib] = a; s_neg[wib] = b; }
        __syncthreads();
        if (threadIdx.x == 0) {
            double sp = 0.0, sn = 0.0;
            #pragma unroll
            for (int w = 0; w < (NTHREADS >> 5); w++) { sp += s_pos[w]; sn += s_neg[w]; }
            const double n_pos_terms = (double)((long long)pos_rows * NCTX);
            const double n_neg_terms = (double)((long long)neg_rows * NCTX);
            out[0] = (float)(sp / n_pos_terms + sn / n_neg_terms);
            g_done = 0;   // self-reset for next graph replay
        }
    }
}

extern "C" void kernel_launch(void* const* d_in, const int* in_sizes, int n_in,
                              void* d_out, int out_size) {
    const float* emb    = (const float*)d_in[0];
    const int*   pos_rw = (const int*)d_in[1];
    const int*   neg_rw = (const int*)d_in[2];
    float*       out    = (float*)d_out;

    const int pos_rows = in_sizes[1] / CTX;   // 200000
    const int neg_rows = in_sizes[2] / CTX;   // 1000000

    mp2v_kernel<<<NBLOCKS, NTHREADS>>>(emb, pos_rw, neg_rw, pos_rows, neg_rows, out);
}

// round 13
// speedup vs baseline: 1.2988x; 1.2988x over previous
#include <cuda_runtime.h>
#include <cuda_fp16.h>

// CustomMetaPath2Vec: loss = mean(-log(sigmoid(pos_dots)+eps)) + mean(-log(1-sigmoid(neg_dots)+eps))
//
// R13: DRAM-TRAFFIC reduction. Two rounds of evidence show a ~6.3 TB/s DRAM
// ceiling for the random 512B-row gather pattern (occupancy 52%->73% moved
// DRAM% 79.2->80.0, dur unchanged). So: convert the 512MB fp32 table to fp16
// into a 256MB __device__ scratch array every call (~110us streaming), then
// gather 256B/row instead of 512B -> request traffic 4.33GB -> 2.18GB and L2
// hit rises (table 256MB vs 126MB L2). Dots accumulate in fp32 from fp16
// inputs: dot error ~6e-3 RMS on dots ~N(0,11.3) -> predicted loss rel_err
// ~1e-5, far inside 1e-3.
//
// LOSS NUMERICS (unchanged, do not touch): s = 1.0f/(1.0f+expf(-x)) with
// accurate expf + true division; pos: -logf(s+1e-15f); neg: -logf(1.0f-s+1e-15f).

#define DIM      128
#define CTX      7
#define NCTX     6
#define EPSF     1e-15f
#define NUM_EMB  1000001
#define NTHREADS 256
#define NBLOCKS  1184       // R7's fastest grid config
#define GROUP    4          // rows per warp iteration (GROUP*CTX = 28 <= 32 lanes)

// 256MB fp16 shadow of the embedding table (static device scratch: legal).
__device__ __align__(16) static __half g_emb_h[(size_t)NUM_EMB * DIM];

__device__ double       g_part_pos[NBLOCKS];
__device__ double       g_part_neg[NBLOCKS];
__device__ unsigned int g_done = 0;   // self-resetting completion counter

// ---- fp32 -> fp16 table conversion (streaming, ~110us) ----
__global__ __launch_bounds__(NTHREADS) void mp2v_convert_kernel(
    const float* __restrict__ emb, int n4)
{
    const float4* __restrict__ src = (const float4*)emb;
    __half2*      __restrict__ dst = (__half2*)g_emb_h;
    int i = blockIdx.x * NTHREADS + threadIdx.x;
    const int stride = gridDim.x * NTHREADS;
    for (; i < n4; i += stride) {
        float4 v = src[i];                       // 16B/lane coalesced read
        dst[2 * i]     = __floats2half2_rn(v.x, v.y);  // 8B/lane coalesced write
        dst[2 * i + 1] = __floats2half2_rn(v.z, v.w);
    }
}

// Coalesced 28-lane index load for one group (group must not straddle the
// pos/neg boundary; caller guarantees or uses the generic path).
__device__ __forceinline__ int load_group_idx(
    const int* __restrict__ pos_rw, const int* __restrict__ neg_rw,
    long long r0, int pos_rows, int lane, int nlanes)
{
    const int* base = (r0 < (long long)pos_rows)
                        ? pos_rw + r0 * CTX
                        : neg_rw + (r0 - pos_rows) * CTX;
    return (lane < nlanes) ? __ldcg(base + lane) : 0;
}

// Gather one lane's 8B (4 halfs) of a 256B embedding row; L2-only caching.
__device__ __forceinline__ uint2 gather_row(int idx, int lane) {
    return __ldcg((const uint2*)(g_emb_h + (size_t)idx * DIM) + lane);
}

__device__ __forceinline__ float dot4_h(uint2 a, uint2 b) {
    float2 a0 = __half22float2(*(const __half2*)&a.x);
    float2 a1 = __half22float2(*(const __half2*)&a.y);
    float2 b0 = __half22float2(*(const __half2*)&b.x);
    float2 b1 = __half22float2(*(const __half2*)&b.y);
    float d = a0.x * b0.x;
    d = fmaf(a0.y, b0.y, d);
    d = fmaf(a1.x, b1.x, d);
    d = fmaf(a1.y, b1.y, d);
    return d;
}

__global__ __launch_bounds__(NTHREADS, 6) void mp2v_kernel(
    const int* __restrict__ pos_rw,
    const int* __restrict__ neg_rw,
    int pos_rows, int neg_rows,
    float* __restrict__ out)
{
    const int lane = threadIdx.x & 31;
    const int wib  = threadIdx.x >> 5;
    const int wpb  = NTHREADS >> 5;

    const long long total   = (long long)pos_rows + neg_rows;
    const long long ngroups = (total + GROUP - 1) / GROUP;
    const long long gstride = (long long)gridDim.x * wpb;
    long long gidx          = (long long)blockIdx.x * wpb + wib;

    const bool uniform = ((pos_rows % GROUP) == 0) && ((total % GROUP) == 0);

    float accp = 0.0f, accn = 0.0f;

    if (uniform) {
        int idx_cur = (gidx < ngroups)
            ? load_group_idx(pos_rw, neg_rw, gidx * GROUP, pos_rows, lane, GROUP * CTX)
            : 0;

        for (long long g = gidx; g < ngroups; g += gstride) {
            const long long gn = g + gstride;
            int idx_nxt = (gn < ngroups)
                ? load_group_idx(pos_rw, neg_rw, gn * GROUP, pos_rows, lane, GROUP * CTX)
                : 0;

            const long long r0 = g * GROUP;
            const bool is_pos  = (r0 < (long long)pos_rows);  // uniform over group

            #pragma unroll
            for (int r = 0; r < GROUP; r++) {
                const int i0 = __shfl_sync(0xffffffffu, idx_cur, r * CTX);
                uint2 h = gather_row(i0, lane);

                uint2 cv[NCTX];
                #pragma unroll
                for (int j = 0; j < NCTX; j++) {
                    const int ij = __shfl_sync(0xffffffffu, idx_cur, r * CTX + j + 1);
                    cv[j] = gather_row(ij, lane);
                }

                float p[NCTX];
                #pragma unroll
                for (int j = 0; j < NCTX; j++)
                    p[j] = dot4_h(h, cv[j]);

                // Butterfly reduce, 6 independent chains (ILP over SHFL latency).
                #pragma unroll
                for (int off = 16; off > 0; off >>= 1) {
                    #pragma unroll
                    for (int j = 0; j < NCTX; j++)
                        p[j] += __shfl_xor_sync(0xffffffffu, p[j], off);
                }

                // Lane j takes dot j; 6-way parallel exp/div/log.
                float x = p[0];
                #pragma unroll
                for (int j = 1; j < NCTX; j++)
                    if (lane == j) x = p[j];

                if (lane < NCTX) {
                    const float s = 1.0f / (1.0f + expf(-x));
                    if (is_pos) accp += -logf(s + EPSF);
                    else        accn += -logf(1.0f - s + EPSF);
                }
            }
            idx_cur = idx_nxt;
        }
    } else {
        // Cold generic path: per-row indexing, handles straddle + tail.
        for (long long g = gidx; g < ngroups; g += gstride) {
            const long long r0 = g * GROUP;
            const int nrows = (int)((total - r0 < GROUP) ? (total - r0) : GROUP);
            int myidx = 0;
            if (lane < nrows * CTX) {
                const int rr = lane / CTX, cc = lane % CTX;
                const long long row = r0 + rr;
                myidx = (row < (long long)pos_rows)
                          ? pos_rw[row * CTX + cc]
                          : neg_rw[(row - pos_rows) * CTX + cc];
            }
            for (int r = 0; r < nrows; r++) {
                const bool is_pos = (r0 + r) < (long long)pos_rows;
                const int i0 = __shfl_sync(0xffffffffu, myidx, r * CTX);
                uint2 h = gather_row(i0, lane);
                uint2 cv[NCTX];
                #pragma unroll
                for (int j = 0; j < NCTX; j++) {
                    const int ij = __shfl_sync(0xffffffffu, myidx, r * CTX + j + 1);
                    cv[j] = gather_row(ij, lane);
                }
                float p[NCTX];
                #pragma unroll
                for (int j = 0; j < NCTX; j++)
                    p[j] = dot4_h(h, cv[j]);
                #pragma unroll
                for (int off = 16; off > 0; off >>= 1) {
                    #pragma unroll
                    for (int j = 0; j < NCTX; j++)
                        p[j] += __shfl_xor_sync(0xffffffffu, p[j], off);
                }
                float x = p[0];
                #pragma unroll
                for (int j = 1; j < NCTX; j++)
                    if (lane == j) x = p[j];
                if (lane < NCTX) {
                    const float s = 1.0f / (1.0f + expf(-x));
                    if (is_pos) accp += -logf(s + EPSF);
                    else        accn += -logf(1.0f - s + EPSF);
                }
            }
        }
    }

    // ---- Block reduction -> per-CTA partial slot ----
    double dp = (double)accp, dn = (double)accn;
    #pragma unroll
    for (int off = 16; off > 0; off >>= 1) {
        dp += __shfl_xor_sync(0xffffffffu, dp, off);
        dn += __shfl_xor_sync(0xffffffffu, dn, off);
    }

    __shared__ double s_pos[NTHREADS >> 5], s_neg[NTHREADS >> 5];
    __shared__ bool   am_last;
    if (lane == 0) { s_pos[wib] = dp; s_neg[wib] = dn; }
    __syncthreads();
    if (threadIdx.x == 0) {
        double sp = 0.0, sn = 0.0;
        #pragma unroll
        for (int w = 0; w < (NTHREADS >> 5); w++) { sp += s_pos[w]; sn += s_neg[w]; }
        g_part_pos[blockIdx.x] = sp;
        g_part_neg[blockIdx.x] = sn;
        __threadfence();
        const unsigned t = atomicAdd(&g_done, 1u);
        am_last = (t == (unsigned)(gridDim.x - 1));
    }
    __syncthreads();

    // ---- Last CTA: final reduction + output + counter reset ----
    if (am_last) {
        __threadfence();  // acquire partials from all CTAs
        double a = 0.0, b = 0.0;
        for (int i = threadIdx.x; i < (int)gridDim.x; i += NTHREADS) {
            a += g_part_pos[i];
            b += g_part_neg[i];
        }
        #pragma unroll
        for (int off = 16; off > 0; off >>= 1) {
            a += __shfl_xor_sync(0xffffffffu, a, off);
            b += __shfl_xor_sync(0xffffffffu, b, off);
        }
        if (lane == 0) { s_pos[wib] = a; s_neg[wib] = b; }
        __syncthreads();
        if (threadIdx.x == 0) {
            double sp = 0.0, sn = 0.0;
            #pragma unroll
            for (int w = 0; w < (NTHREADS >> 5); w++) { sp += s_pos[w]; sn += s_neg[w]; }
            const double n_pos_terms = (double)((long long)pos_rows * NCTX);
            const double n_neg_terms = (double)((long long)neg_rows * NCTX);
            out[0] = (float)(sp / n_pos_terms + sn / n_neg_terms);
            g_done = 0;   // self-reset for next graph replay
        }
    }
}

extern "C" void kernel_launch(void* const* d_in, const int* in_sizes, int n_in,
                              void* d_out, int out_size) {
    const float* emb    = (const float*)d_in[0];
    const int*   pos_rw = (const int*)d_in[1];
    const int*   neg_rw = (const int*)d_in[2];
    float*       out    = (float*)d_out;

    const int pos_rows = in_sizes[1] / CTX;   // 200000
    const int neg_rows = in_sizes[2] / CTX;   // 1000000
    const int n4       = in_sizes[0] / 4;     // float4 count of emb table

    // 1) fp32 -> fp16 table shadow (stream-ordered before the main kernel)
    mp2v_convert_kernel<<<888, NTHREADS>>>(emb, n4);
    // 2) gather + dot + loss + fused finalize
    mp2v_kernel<<<NBLOCKS, NTHREADS>>>(pos_rw, neg_rw, pos_rows, neg_rows, out);
}

// round 14
// speedup vs baseline: 1.3531x; 1.0418x over previous
#include <cuda_runtime.h>
#include <cuda_fp16.h>

// CustomMetaPath2Vec: loss = mean(-log(sigmoid(pos_dots)+eps)) + mean(-log(1-sigmoid(neg_dots)+eps))
//
// R14: main kernel was ISSUE-bound (issue 67.1%, DRAM 55.1%, ~180 instr/row).
// Cuts: (1) HFMA2 half2 dot partials (kills 48 H2F converts/row),
// (2) butterfly on 3 packed half2 regs (30 instr vs 60),
// (3) loss/transcendental block amortized over 4 rows (24 active lanes once
//     per group instead of 6 lanes every row; accurate expf/div/logf are
//     multi-instr sequences the whole warp must issue).
// Expected ~84 instr/row -> memory-side floor (~240us) becomes binding again.
//
// LOSS NUMERICS (unchanged, do not touch): fp32 s = 1.0f/(1.0f+expf(-x)),
// accurate expf + true division; pos: -logf(s+1e-15f); neg: -logf(1.0f-s+1e-15f).
// fp16 gather+accumулation adds ~0.01 RMS to dots -> predicted rel_err 2-5e-5.

#define DIM      128
#define CTX      7
#define NCTX     6
#define EPSF     1e-15f
#define NUM_EMB  1000001
#define NTHREADS 256
#define NBLOCKS  1184
#define GROUP    4          // rows per warp iteration (GROUP*CTX = 28 <= 32 lanes)

// 256MB fp16 shadow of the embedding table (static device scratch: legal).
__device__ __align__(16) static __half g_emb_h[(size_t)NUM_EMB * DIM];

__device__ double       g_part_pos[NBLOCKS];
__device__ double       g_part_neg[NBLOCKS];
__device__ unsigned int g_done = 0;   // self-resetting completion counter

// ---- fp32 -> fp16 table conversion (streaming, ~110us) ----
__global__ __launch_bounds__(NTHREADS) void mp2v_convert_kernel(
    const float* __restrict__ emb, int n4)
{
    const float4* __restrict__ src = (const float4*)emb;
    __half2*      __restrict__ dst = (__half2*)g_emb_h;
    int i = blockIdx.x * NTHREADS + threadIdx.x;
    const int stride = gridDim.x * NTHREADS;
    for (; i < n4; i += stride) {
        float4 v = src[i];
        dst[2 * i]     = __floats2half2_rn(v.x, v.y);
        dst[2 * i + 1] = __floats2half2_rn(v.z, v.w);
    }
}

__device__ __forceinline__ int load_group_idx(
    const int* __restrict__ pos_rw, const int* __restrict__ neg_rw,
    long long r0, int pos_rows, int lane, int nlanes)
{
    const int* base = (r0 < (long long)pos_rows)
                        ? pos_rw + r0 * CTX
                        : neg_rw + (r0 - pos_rows) * CTX;
    return (lane < nlanes) ? __ldcg(base + lane) : 0;
}

// One lane's 8B (4 halfs) of a 256B embedding row; L2-only caching.
__device__ __forceinline__ uint2 gather_row(int idx, int lane) {
    return __ldcg((const uint2*)(g_emb_h + (size_t)idx * DIM) + lane);
}

__device__ __forceinline__ __half2 shfl_xor_h2(__half2 v, int off) {
    unsigned u = *reinterpret_cast<unsigned*>(&v);
    u = __shfl_xor_sync(0xffffffffu, u, off);
    return *reinterpret_cast<__half2*>(&u);
}

// Per-lane 4-elem dot in fp16: q = h01*c01 + h23*c23 (pairwise), then horizontal.
__device__ __forceinline__ __half dot4_h16(__half2 h01, __half2 h23, uint2 c) {
    __half2 c01 = *reinterpret_cast<__half2*>(&c.x);
    __half2 c23 = *reinterpret_cast<__half2*>(&c.y);
    __half2 q = __hfma2(h01, c01, __hmul2(h23, c23));
    return __hadd(__low2half(q), __high2half(q));
}

// Loss term in exact fp32 reference formulation.
__device__ __forceinline__ void loss_term(float x, bool is_pos,
                                          float& accp, float& accn) {
    const float s = 1.0f / (1.0f + expf(-x));
    if (is_pos) accp += -logf(s + EPSF);
    else        accn += -logf(1.0f - s + EPSF);
}

__global__ __launch_bounds__(NTHREADS, 6) void mp2v_kernel(
    const int* __restrict__ pos_rw,
    const int* __restrict__ neg_rw,
    int pos_rows, int neg_rows,
    float* __restrict__ out)
{
    const int lane = threadIdx.x & 31;
    const int wib  = threadIdx.x >> 5;
    const int wpb  = NTHREADS >> 5;
    const int lane_row  = lane / NCTX;   // which row of the group this lane owns
    const int lane_dot  = lane % NCTX;   // which dot of that row

    const long long total   = (long long)pos_rows + neg_rows;
    const long long ngroups = (total + GROUP - 1) / GROUP;
    const long long gstride = (long long)gridDim.x * wpb;
    long long gidx          = (long long)blockIdx.x * wpb + wib;

    const bool uniform = ((pos_rows % GROUP) == 0) && ((total % GROUP) == 0);

    float accp = 0.0f, accn = 0.0f;

    if (uniform) {
        int idx_cur = (gidx < ngroups)
            ? load_group_idx(pos_rw, neg_rw, gidx * GROUP, pos_rows, lane, GROUP * CTX)
            : 0;

        for (long long g = gidx; g < ngroups; g += gstride) {
            const long long gn = g + gstride;
            int idx_nxt = (gn < ngroups)
                ? load_group_idx(pos_rw, neg_rw, gn * GROUP, pos_rows, lane, GROUP * CTX)
                : 0;

            const long long r0 = g * GROUP;
            const bool is_pos  = (r0 < (long long)pos_rows);  // uniform over group

            __half my_x = __float2half(0.0f);

            #pragma unroll
            for (int r = 0; r < GROUP; r++) {
                const int i0 = __shfl_sync(0xffffffffu, idx_cur, r * CTX);
                uint2 hraw = gather_row(i0, lane);
                __half2 h01 = *reinterpret_cast<__half2*>(&hraw.x);
                __half2 h23 = *reinterpret_cast<__half2*>(&hraw.y);

                uint2 cv[NCTX];
                #pragma unroll
                for (int j = 0; j < NCTX; j++) {
                    const int ij = __shfl_sync(0xffffffffu, idx_cur, r * CTX + j + 1);
                    cv[j] = gather_row(ij, lane);
                }

                // 6 per-lane partials -> 3 packed half2.
                __half rj[NCTX];
                #pragma unroll
                for (int j = 0; j < NCTX; j++)
                    rj[j] = dot4_h16(h01, h23, cv[j]);
                __half2 S0 = __halves2half2(rj[0], rj[1]);
                __half2 S1 = __halves2half2(rj[2], rj[3]);
                __half2 S2 = __halves2half2(rj[4], rj[5]);

                // Butterfly reduce on 3 half2 regs (all lanes end with full sums).
                #pragma unroll
                for (int off = 16; off > 0; off >>= 1) {
                    S0 = __hadd2(S0, shfl_xor_h2(S0, off));
                    S1 = __hadd2(S1, shfl_xor_h2(S1, off));
                    S2 = __hadd2(S2, shfl_xor_h2(S2, off));
                }

                // Lane l (<24) captures dot (l%6) of row (l/6).
                if (lane_row == r) {
                    __half2 sel = (lane_dot < 2) ? S0 : ((lane_dot < 4) ? S1 : S2);
                    my_x = (lane_dot & 1) ? __high2half(sel) : __low2half(sel);
                }
            }

            // One transcendental block per 4 rows, 24 active lanes.
            if (lane < GROUP * NCTX)
                loss_term(__half2float(my_x), is_pos, accp, accn);

            idx_cur = idx_nxt;
        }
    } else {
        // Cold generic path (unused for this dataset): per-row, handles straddle+tail.
        for (long long g = gidx; g < ngroups; g += gstride) {
            const long long r0 = g * GROUP;
            const int nrows = (int)((total - r0 < GROUP) ? (total - r0) : GROUP);
            int myidx = 0;
            if (lane < nrows * CTX) {
                const int rr = lane / CTX, cc = lane % CTX;
                const long long row = r0 + rr;
                myidx = (row < (long long)pos_rows)
                          ? pos_rw[row * CTX + cc]
                          : neg_rw[(row - pos_rows) * CTX + cc];
            }
            for (int r = 0; r < nrows; r++) {
                const bool is_pos = (r0 + r) < (long long)pos_rows;
                const int i0 = __shfl_sync(0xffffffffu, myidx, r * CTX);
                uint2 hraw = gather_row(i0, lane);
                __half2 h01 = *reinterpret_cast<__half2*>(&hraw.x);
                __half2 h23 = *reinterpret_cast<__half2*>(&hraw.y);
                uint2 cv[NCTX];
                #pragma unroll
                for (int j = 0; j < NCTX; j++) {
                    const int ij = __shfl_sync(0xffffffffu, myidx, r * CTX + j + 1);
                    cv[j] = gather_row(ij, lane);
                }
                __half rj[NCTX];
                #pragma unroll
                for (int j = 0; j < NCTX; j++)
                    rj[j] = dot4_h16(h01, h23, cv[j]);
                __half2 S0 = __halves2half2(rj[0], rj[1]);
                __half2 S1 = __halves2half2(rj[2], rj[3]);
                __half2 S2 = __halves2half2(rj[4], rj[5]);
                #pragma unroll
                for (int off = 16; off > 0; off >>= 1) {
                    S0 = __hadd2(S0, shfl_xor_h2(S0, off));
                    S1 = __hadd2(S1, shfl_xor_h2(S1, off));
                    S2 = __hadd2(S2, shfl_xor_h2(S2, off));
                }
                if (lane < NCTX) {
                    __half2 sel = (lane < 2) ? S0 : ((lane < 4) ? S1 : S2);
                    __half xh = (lane & 1) ? __high2half(sel) : __low2half(sel);
                    loss_term(__half2float(xh), is_pos, accp, accn);
                }
            }
        }
    }

    // ---- Block reduction -> per-CTA partial slot ----
    double dp = (double)accp, dn = (double)accn;
    #pragma unroll
    for (int off = 16; off > 0; off >>= 1) {
        dp += __shfl_xor_sync(0xffffffffu, dp, off);
        dn += __shfl_xor_sync(0xffffffffu, dn, off);
    }

    __shared__ double s_pos[NTHREADS >> 5], s_neg[NTHREADS >> 5];
    __shared__ bool   am_last;
    if (lane == 0) { s_pos[wib] = dp; s_neg[wib] = dn; }
    __syncthreads();
    if (threadIdx.x == 0) {
        double sp = 0.0, sn = 0.0;
        #pragma unroll
        for (int w = 0; w < (NTHREADS >> 5); w++) { sp += s_pos[w]; sn += s_neg[w]; }
        g_part_pos[blockIdx.x] = sp;
        g_part_neg[blockIdx.x] = sn;
        __threadfence();
        const unsigned t = atomicAdd(&g_done, 1u);
        am_last = (t == (unsigned)(gridDim.x - 1));
    }
    __syncthreads();

    // ---- Last CTA: final reduction + output + counter reset ----
    if (am_last) {
        __threadfence();
        double a = 0.0, b = 0.0;
        for (int i = threadIdx.x; i < (int)gridDim.x; i += NTHREADS) {
            a += g_part_pos[i];
            b += g_part_neg[i];
        }
        #pragma unroll
        for (int off = 16; off > 0; off >>= 1) {
            a += __shfl_xor_sync(0xffffffffu, a, off);
            b += __shfl_xor_sync(0xffffffffu, b, off);
        }
        if (lane == 0) { s_pos[wib] = a; s_neg[wib] = b; }
        __syncthreads();
        if (threadIdx.x == 0) {
            double sp = 0.0, sn = 0.0;
            #pragma unroll
            for (int w = 0; w < (NTHREADS >> 5); w++) { sp += s_pos[w]; sn += s_neg[w]; }
            const double n_pos_terms = (double)((long long)pos_rows * NCTX);
            const double n_neg_terms = (double)((long long)neg_rows * NCTX);
            out[0] = (float)(sp / n_pos_terms + sn / n_neg_terms);
            g_done = 0;   // self-reset for next graph replay
        }
    }
}

extern "C" void kernel_launch(void* const* d_in, const int* in_sizes, int n_in,
                              void* d_out, int out_size) {
    const float* emb    = (const float*)d_in[0];
    const int*   pos_rw = (const int*)d_in[1];
    const int*   neg_rw = (const int*)d_in[2];
    float*       out    = (float*)d_out;

    const int pos_rows = in_sizes[1] / CTX;   // 200000
    const int neg_rows = in_sizes[2] / CTX;   // 1000000
    const int n4       = in_sizes[0] / 4;     // float4 count of emb table

    mp2v_convert_kernel<<<888, NTHREADS>>>(emb, n4);
    mp2v_kernel<<<NBLOCKS, NTHREADS>>>(pos_rw, neg_rw, pos_rows, neg_rows, out);
}

// round 15
// speedup vs baseline: 1.6804x; 1.2419x over previous
#include <cuda_runtime.h>
#include <cuda_fp16.h>

// CustomMetaPath2Vec: loss = mean(-log(sigmoid(pos_dots)+eps)) + mean(-log(1-sigmoid(neg_dots)+eps))
//
// R15: main kernel was LATENCY-bound (DRAM 58.5%, issue 37.9% -> neither pipe
// saturated). Structural fix: row-pair lane split. Each fp16 row is 256B; each
// lane now loads 16B (uint4, 8 halfs) so a row needs 16 lanes. Lanes 0-15
// process row A while lanes 16-31 process row B:
//   - 7x LDG.128 per PAIR (was 7x LDG.64 per row): gather instrs halved
//   - butterfly: 4 stages within 16-lane halves, serves 2 rows at once
//   - ~40 instr/row (was ~84), serial reduce depth per row ~2.6x lower
// Grid = 888 = exactly one resident wave (6 CTAs/SM) -> no ragged tail.
//
// LOSS NUMERICS (unchanged, do not touch): fp32 s = 1.0f/(1.0f+expf(-x)) with
// accurate expf + true division; pos: -logf(s+1e-15f); neg: -logf(1.0f-s+1e-15f).

#define DIM      128
#define CTX      7
#define NCTX     6
#define EPSF     1e-15f
#define NUM_EMB  1000001
#define NTHREADS 256
#define NBLOCKS  888        // 148 SMs * 6 CTAs/SM = one resident wave
#define GROUP    4          // rows per warp iteration (GROUP*CTX = 28 idx lanes)

// 256MB fp16 shadow of the embedding table (static device scratch: legal).
__device__ __align__(16) static __half g_emb_h[(size_t)NUM_EMB * DIM];

__device__ double       g_part_pos[NBLOCKS];
__device__ double       g_part_neg[NBLOCKS];
__device__ unsigned int g_done = 0;   // self-resetting completion counter

// ---- fp32 -> fp16 table conversion (streaming, ~110us) ----
__global__ __launch_bounds__(NTHREADS) void mp2v_convert_kernel(
    const float* __restrict__ emb, int n4)
{
    const float4* __restrict__ src = (const float4*)emb;
    __half2*      __restrict__ dst = (__half2*)g_emb_h;
    int i = blockIdx.x * NTHREADS + threadIdx.x;
    const int stride = gridDim.x * NTHREADS;
    for (; i < n4; i += stride) {
        float4 v = src[i];
        dst[2 * i]     = __floats2half2_rn(v.x, v.y);
        dst[2 * i + 1] = __floats2half2_rn(v.z, v.w);
    }
}

__device__ __forceinline__ int load_group_idx(
    const int* __restrict__ pos_rw, const int* __restrict__ neg_rw,
    long long r0, int pos_rows, int lane, int nlanes)
{
    const int* base = (r0 < (long long)pos_rows)
                        ? pos_rw + r0 * CTX
                        : neg_rw + (r0 - pos_rows) * CTX;
    return (lane < nlanes) ? __ldcg(base + lane) : 0;
}

// One lane's 16B (8 halfs) of a 256B embedding row; L2-only caching.
__device__ __forceinline__ uint4 gather_row16(int idx, int sub) {
    return __ldcg((const uint4*)(g_emb_h + (size_t)idx * DIM) + sub);
}

__device__ __forceinline__ __half2 shfl_xor_h2(__half2 v, int off) {
    unsigned u = *reinterpret_cast<unsigned*>(&v);
    u = __shfl_xor_sync(0xffffffffu, u, off);
    return *reinterpret_cast<__half2*>(&u);
}

// 8-elem per-lane dot in fp16: 1 HMUL2 + 3 HFMA2 + horizontal.
__device__ __forceinline__ __half dot8_h16(uint4 a, uint4 b) {
    __half2 a0 = *reinterpret_cast<__half2*>(&a.x);
    __half2 a1 = *reinterpret_cast<__half2*>(&a.y);
    __half2 a2 = *reinterpret_cast<__half2*>(&a.z);
    __half2 a3 = *reinterpret_cast<__half2*>(&a.w);
    __half2 b0 = *reinterpret_cast<__half2*>(&b.x);
    __half2 b1 = *reinterpret_cast<__half2*>(&b.y);
    __half2 b2 = *reinterpret_cast<__half2*>(&b.z);
    __half2 b3 = *reinterpret_cast<__half2*>(&b.w);
    __half2 q = __hmul2(a0, b0);
    q = __hfma2(a1, b1, q);
    q = __hfma2(a2, b2, q);
    q = __hfma2(a3, b3, q);
    return __hadd(__low2half(q), __high2half(q));
}

// Loss term in exact fp32 reference formulation.
__device__ __forceinline__ void loss_term(float x, bool is_pos,
                                          float& accp, float& accn) {
    const float s = 1.0f / (1.0f + expf(-x));
    if (is_pos) accp += -logf(s + EPSF);
    else        accn += -logf(1.0f - s + EPSF);
}

__global__ __launch_bounds__(NTHREADS, 6) void mp2v_kernel(
    const int* __restrict__ pos_rw,
    const int* __restrict__ neg_rw,
    int pos_rows, int neg_rows,
    float* __restrict__ out)
{
    const int lane = threadIdx.x & 31;
    const int wib  = threadIdx.x >> 5;
    const int wpb  = NTHREADS >> 5;
    const int half = lane >> 4;          // 0: row A of pair, 1: row B
    const int sub  = lane & 15;          // 16B chunk within the row
    const int lane_row = lane / NCTX;    // capture mapping: row of group
    const int lane_dot = lane % NCTX;    // capture mapping: dot of row

    const long long total   = (long long)pos_rows + neg_rows;
    const long long ngroups = (total + GROUP - 1) / GROUP;
    const long long gstride = (long long)gridDim.x * wpb;
    long long gidx          = (long long)blockIdx.x * wpb + wib;

    const bool uniform = ((pos_rows % GROUP) == 0) && ((total % GROUP) == 0);

    float accp = 0.0f, accn = 0.0f;

    if (uniform) {
        int idx_cur = (gidx < ngroups)
            ? load_group_idx(pos_rw, neg_rw, gidx * GROUP, pos_rows, lane, GROUP * CTX)
            : 0;

        for (long long g = gidx; g < ngroups; g += gstride) {
            const long long gn = g + gstride;
            int idx_nxt = (gn < ngroups)
                ? load_group_idx(pos_rw, neg_rw, gn * GROUP, pos_rows, lane, GROUP * CTX)
                : 0;

            const long long r0 = g * GROUP;
            const bool is_pos  = (r0 < (long long)pos_rows);  // uniform over group

            __half my_x = __float2half(0.0f);

            // Two row-pairs per group: lanes 0-15 do row 2t, lanes 16-31 row 2t+1.
            #pragma unroll
            for (int t = 0; t < GROUP / 2; t++) {
                const int rowbase = 2 * t + half;

                const int i0 = __shfl_sync(0xffffffffu, idx_cur, rowbase * CTX);
                uint4 h = gather_row16(i0, sub);

                uint4 cv[NCTX];
                #pragma unroll
                for (int j = 0; j < NCTX; j++) {
                    const int ij = __shfl_sync(0xffffffffu, idx_cur,
                                               rowbase * CTX + j + 1);
                    cv[j] = gather_row16(ij, sub);
                }

                // 6 per-lane 8-elem partials -> 3 packed half2.
                __half rj[NCTX];
                #pragma unroll
                for (int j = 0; j < NCTX; j++)
                    rj[j] = dot8_h16(h, cv[j]);
                __half2 S0 = __halves2half2(rj[0], rj[1]);
                __half2 S1 = __halves2half2(rj[2], rj[3]);
                __half2 S2 = __halves2half2(rj[4], rj[5]);

                // 4-stage butterfly, stays inside each 16-lane half.
                #pragma unroll
                for (int off = 8; off > 0; off >>= 1) {
                    S0 = __hadd2(S0, shfl_xor_h2(S0, off));
                    S1 = __hadd2(S1, shfl_xor_h2(S1, off));
                    S2 = __hadd2(S2, shfl_xor_h2(S2, off));
                }

                // Lanes k<6 of each half pre-select dot k of their half's row;
                // capture lane l pulls from src = ((row&1)<<4) | (l%6).
                __half2 sel = (sub < 2) ? S0 : ((sub < 4) ? S1 : S2);
                __half xk = (sub & 1) ? __high2half(sel) : __low2half(sel);
                unsigned xu = (unsigned)__half_as_ushort(xk);
                unsigned got = __shfl_sync(0xffffffffu, xu,
                                           ((lane_row & 1) << 4) | lane_dot);
                if ((lane_row >> 1) == t)   // lanes >= 24 have lane_row >= 4: never
                    my_x = __ushort_as_half((unsigned short)got);
            }

            // One transcendental block per 4 rows, 24 active lanes.
            if (lane < GROUP * NCTX)
                loss_term(__half2float(my_x), is_pos, accp, accn);

            idx_cur = idx_nxt;
        }
    } else {
        // Cold generic path (unused for this dataset): per-row uint2 scheme,
        // handles straddle + tail.
        for (long long g = gidx; g < ngroups; g += gstride) {
            const long long r0 = g * GROUP;
            const int nrows = (int)((total - r0 < GROUP) ? (total - r0) : GROUP);
            int myidx = 0;
            if (lane < nrows * CTX) {
                const int rr = lane / CTX, cc = lane % CTX;
                const long long row = r0 + rr;
                myidx = (row < (long long)pos_rows)
                          ? pos_rw[row * CTX + cc]
                          : neg_rw[(row - pos_rows) * CTX + cc];
            }
            for (int r = 0; r < nrows; r++) {
                const bool is_pos = (r0 + r) < (long long)pos_rows;
                const int i0 = __shfl_sync(0xffffffffu, myidx, r * CTX);
                uint2 hraw = __ldcg((const uint2*)(g_emb_h + (size_t)i0 * DIM) + lane);
                __half2 h01 = *reinterpret_cast<__half2*>(&hraw.x);
                __half2 h23 = *reinterpret_cast<__half2*>(&hraw.y);
                __half rj[NCTX];
                #pragma unroll
                for (int j = 0; j < NCTX; j++) {
                    const int ij = __shfl_sync(0xffffffffu, myidx, r * CTX + j + 1);
                    uint2 c = __ldcg((const uint2*)(g_emb_h + (size_t)ij * DIM) + lane);
                    __half2 c01 = *reinterpret_cast<__half2*>(&c.x);
                    __half2 c23 = *reinterpret_cast<__half2*>(&c.y);
                    __half2 q = __hfma2(h01, c01, __hmul2(h23, c23));
                    rj[j] = __hadd(__low2half(q), __high2half(q));
                }
                __half2 S0 = __halves2half2(rj[0], rj[1]);
                __half2 S1 = __halves2half2(rj[2], rj[3]);
                __half2 S2 = __halves2half2(rj[4], rj[5]);
                #pragma unroll
                for (int off = 16; off > 0; off >>= 1) {
                    S0 = __hadd2(S0, shfl_xor_h2(S0, off));
                    S1 = __hadd2(S1, shfl_xor_h2(S1, off));
                    S2 = __hadd2(S2, shfl_xor_h2(S2, off));
                }
                if (lane < NCTX) {
                    __half2 sel = (lane < 2) ? S0 : ((lane < 4) ? S1 : S2);
                    __half xh = (lane & 1) ? __high2half(sel) : __low2half(sel);
                    loss_term(__half2float(xh), is_pos, accp, accn);
                }
            }
        }
    }

    // ---- Block reduction -> per-CTA partial slot ----
    double dp = (double)accp, dn = (double)accn;
    #pragma unroll
    for (int off = 16; off > 0; off >>= 1) {
        dp += __shfl_xor_sync(0xffffffffu, dp, off);
        dn += __shfl_xor_sync(0xffffffffu, dn, off);
    }

    __shared__ double s_pos[NTHREADS >> 5], s_neg[NTHREADS >> 5];
    __shared__ bool   am_last;
    if (lane == 0) { s_pos[wib] = dp; s_neg[wib] = dn; }
    __syncthreads();
    if (threadIdx.x == 0) {
        double sp = 0.0, sn = 0.0;
        #pragma unroll
        for (int w = 0; w < (NTHREADS >> 5); w++) { sp += s_pos[w]; sn += s_neg[w]; }
        g_part_pos[blockIdx.x] = sp;
        g_part_neg[blockIdx.x] = sn;
        __threadfence();
        const unsigned t = atomicAdd(&g_done, 1u);
        am_last = (t == (unsigned)(gridDim.x - 1));
    }
    __syncthreads();

    // ---- Last CTA: final reduction + output + counter reset ----
    if (am_last) {
        __threadfence();
        double a = 0.0, b = 0.0;
        for (int i = threadIdx.x; i < (int)gridDim.x; i += NTHREADS) {
            a += g_part_pos[i];
            b += g_part_neg[i];
        }
        #pragma unroll
        for (int off = 16; off > 0; off >>= 1) {
            a += __shfl_xor_sync(0xffffffffu, a, off);
            b += __shfl_xor_sync(0xffffffffu, b, off);
        }
        if (lane == 0) { s_pos[wib] = a; s_neg[wib] = b; }
        __syncthreads();
        if (threadIdx.x == 0) {
            double sp = 0.0, sn = 0.0;
            #pragma unroll
            for (int w = 0; w < (NTHREADS >> 5); w++) { sp += s_pos[w]; sn += s_neg[w]; }
            const double n_pos_terms = (double)((long long)pos_rows * NCTX);
            const double n_neg_terms = (double)((long long)neg_rows * NCTX);
            out[0] = (float)(sp / n_pos_terms + sn / n_neg_terms);
            g_done = 0;   // self-reset for next graph replay
        }
    }
}

extern "C" void kernel_launch(void* const* d_in, const int* in_sizes, int n_in,
                              void* d_out, int out_size) {
    const float* emb    = (const float*)d_in[0];
    const int*   pos_rw = (const int*)d_in[1];
    const int*   neg_rw = (const int*)d_in[2];
    float*       out    = (float*)d_out;

    const int pos_rows = in_sizes[1] / CTX;   // 200000
    const int neg_rows = in_sizes[2] / CTX;   // 1000000
    const int n4       = in_sizes[0] / 4;     // float4 count of emb table

    mp2v_convert_kernel<<<888, NTHREADS>>>(emb, n4);
    mp2v_kernel<<<NBLOCKS, NTHREADS>>>(pos_rw, neg_rw, pos_rows, neg_rows, out);
}